// round 9
// baseline (speedup 1.0000x reference)
#include <cuda_runtime.h>
#include <cuda_fp16.h>
#include <math.h>
#include <stdint.h>

#define B_   2
#define S_   2048
#define H_   2048
#define NH_  16
#define NKV_ 4
#define HD_  128
#define M_   (B_*S_)   // 4096

// ---------------------------------------------------------------------------
// Scratch (no allocations allowed) — device globals.
// ---------------------------------------------------------------------------
__device__ float  g_q[(size_t)M_ * NH_ * HD_];      // fp32 Q proj
__device__ float  g_k[(size_t)M_ * NKV_ * HD_];     // fp32 K proj
__device__ __half g_qh[(size_t)M_ * NH_ * HD_];     // fp16 post-norm/rope
__device__ __half g_kh[(size_t)M_ * NKV_ * HD_];
__device__ __half g_vh[(size_t)M_ * NKV_ * HD_];    // fp16 V proj (direct)
__device__ __half g_attn_h[(size_t)M_ * NH_ * HD_];
__device__ __half g_hs_h[(size_t)M_ * H_];
__device__ __half g_wqkv_h[(size_t)3072 * H_];      // [Wq;Wk;Wv] concat rows
__device__ __half g_wo_h[(size_t)H_ * (NH_*HD_)];

// ---------------------------------------------------------------------------
// PTX helpers
// ---------------------------------------------------------------------------
__device__ __forceinline__ uint32_t smem_u32(const void* p) {
    uint32_t a;
    asm("{ .reg .u64 t; cvta.to.shared.u64 t, %1; cvt.u32.u64 %0, t; }"
        : "=r"(a) : "l"(p));
    return a;
}
__device__ __forceinline__ uint32_t swz(uint32_t off) {   // 128B-row swizzle
    return off ^ ((off >> 3) & 0x70);
}
__device__ __forceinline__ void mma16816(float* d, const uint32_t* a,
                                         const uint32_t* b)
{
    asm volatile(
        "mma.sync.aligned.m16n8k16.row.col.f32.f16.f16.f32 "
        "{%0,%1,%2,%3}, {%4,%5,%6,%7}, {%8,%9}, {%0,%1,%2,%3};"
        : "+f"(d[0]), "+f"(d[1]), "+f"(d[2]), "+f"(d[3])
        : "r"(a[0]), "r"(a[1]), "r"(a[2]), "r"(a[3]), "r"(b[0]), "r"(b[1]));
}
__device__ __forceinline__ void ldmx4(uint32_t* r, uint32_t addr) {
    asm volatile("ldmatrix.sync.aligned.m8n8.x4.shared.b16 {%0,%1,%2,%3}, [%4];"
                 : "=r"(r[0]), "=r"(r[1]), "=r"(r[2]), "=r"(r[3]) : "r"(addr));
}
__device__ __forceinline__ void ldmx4t(uint32_t* r, uint32_t addr) {
    asm volatile("ldmatrix.sync.aligned.m8n8.x4.trans.shared.b16 {%0,%1,%2,%3}, [%4];"
                 : "=r"(r[0]), "=r"(r[1]), "=r"(r[2]), "=r"(r[3]) : "r"(addr));
}

// ---------------------------------------------------------------------------
// GEMM core, register-staged LDG.128+STS.128 (cp.async/LDGSTS is the slow
// path on this chip — flash3's LDG+STS sustains ~2x the fill rate).
// 3 smem buffers x (A 16KB + B 16KB) = 96KB; one __syncthreads per k64 stage:
//   iter s: STS(s+1 from regs) -> LDG(s+2 into regs) -> sync -> compute(s)
// WAR distance 2 mod 3 => safe. K multiple of 64, >= 192.
// ---------------------------------------------------------------------------
#define GEMMH_SMEM 98304

struct GemmAcc { float a[2][8][4]; };

__device__ __forceinline__ void gemm_core(const __half* __restrict__ A,
                                          const __half* __restrict__ Bw,
                                          char* __restrict__ smp,
                                          int K, int m0, int n0,
                                          uint32_t base, GemmAcc& acc)
{
    const int tid = threadIdx.x;
    const int lane = tid & 31, wid = tid >> 5;
    const int wr = (wid >> 1) << 5;
    const int wc = (wid & 1) << 6;
    const int KST = K >> 6;
    const int crow = tid >> 3, cc = tid & 7;     // copy coords: 32 rows x 8 chunks
    const __half* Aptr = A  + (size_t)(m0 + crow) * K + (cc << 3);
    const __half* Bptr = Bw + (size_t)(n0 + crow) * K + (cc << 3);

    uint4 ra[4], rb[4];
    auto do_ldg = [&](int s) {
        const __half* ap = Aptr + (s << 6);
        const __half* bp = Bptr + (s << 6);
#pragma unroll
        for (int i = 0; i < 4; i++) {
            ra[i] = *(const uint4*)(ap + (size_t)(i << 5) * K);
            rb[i] = *(const uint4*)(bp + (size_t)(i << 5) * K);
        }
    };
    auto do_sts = [&](int s) {
        const int buf = s % 3;
        char* ab = smp + buf * 32768;
        char* bb = ab + 16384;
#pragma unroll
        for (int i = 0; i < 4; i++) {
            uint32_t so = swz((uint32_t)((crow + (i << 5)) << 7) + (cc << 4));
            *(uint4*)(ab + so) = ra[i];
            *(uint4*)(bb + so) = rb[i];
        }
    };

#pragma unroll
    for (int mi = 0; mi < 2; mi++)
#pragma unroll
        for (int ni = 0; ni < 8; ni++)
#pragma unroll
            for (int e = 0; e < 4; e++) acc.a[mi][ni][e] = 0.f;

    do_ldg(0);
    do_sts(0);
    do_ldg(1);
    __syncthreads();

    const int ql = lane >> 3, rowin = lane & 7;

    for (int s = 0; s < KST; s++) {
        if (s + 1 < KST) {
            do_sts(s + 1);
            if (s + 2 < KST) do_ldg(s + 2);
        }
        __syncthreads();
        const int buf = s % 3;
        const uint32_t ab = base + buf * 32768u;
        const uint32_t bb = ab + 16384u;
#pragma unroll
        for (int k16 = 0; k16 < 4; k16++) {
            const uint32_t kb = (uint32_t)(k16 << 5);
            uint32_t af[2][4], bf[8][2];
#pragma unroll
            for (int mi = 0; mi < 2; mi++) {
                int row = wr + (mi << 4) + rowin + ((ql & 1) << 3);
                uint32_t off = (uint32_t)(row << 7) + kb + ((uint32_t)(ql >> 1) << 4);
                ldmx4(af[mi], ab + swz(off));
            }
#pragma unroll
            for (int j = 0; j < 4; j++) {
                int row = wc + (j << 4) + rowin + ((ql >> 1) << 3);
                uint32_t off = (uint32_t)(row << 7) + kb + ((uint32_t)(ql & 1) << 4);
                uint32_t r[4];
                ldmx4(r, bb + swz(off));
                bf[2*j][0] = r[0]; bf[2*j][1] = r[1];
                bf[2*j+1][0] = r[2]; bf[2*j+1][1] = r[3];
            }
#pragma unroll
            for (int mi = 0; mi < 2; mi++)
#pragma unroll
                for (int ni = 0; ni < 8; ni++)
                    mma16816(acc.a[mi][ni], af[mi], bf[ni]);
        }
        __syncthreads();   // compute(s) done before next iter overwrites buf s+3-3
    }
}

// Generic fp32-output GEMM: C[M,N] = A @ Bw^T
__global__ void __launch_bounds__(256) gemm_h(const __half* __restrict__ A,
                                              const __half* __restrict__ Bw,
                                              float* __restrict__ C,
                                              int N, int K)
{
    extern __shared__ char smh[];
    const uint32_t base = smem_u32(smh);
    const int m0 = blockIdx.y << 7, n0 = blockIdx.x << 7;
    GemmAcc acc;
    gemm_core(A, Bw, smh, K, m0, n0, base, acc);

    const int lane = threadIdx.x & 31, wid = threadIdx.x >> 5;
    const int wr = (wid >> 1) << 5, wc = (wid & 1) << 6;
    const int lr = lane >> 2, lc = lane & 3;
#pragma unroll
    for (int mi = 0; mi < 2; mi++) {
        const int row = m0 + wr + (mi << 4) + lr;
#pragma unroll
        for (int ni = 0; ni < 8; ni++) {
            const int col = n0 + wc + (ni << 3) + (lc << 1);
            float2 v0 = { acc.a[mi][ni][0], acc.a[mi][ni][1] };
            float2 v1 = { acc.a[mi][ni][2], acc.a[mi][ni][3] };
            *(float2*)(C + (size_t)row * N + col) = v0;
            *(float2*)(C + (size_t)(row + 8) * N + col) = v1;
        }
    }
}

// Fused QKV projection: Bw = [Wq;Wk;Wv] (3072 rows). Output routed per n0.
__global__ void __launch_bounds__(256) gemm_qkv(const __half* __restrict__ A,
                                                const __half* __restrict__ Bw,
                                                float* __restrict__ Q,
                                                float* __restrict__ Kp,
                                                __half* __restrict__ Vh)
{
    extern __shared__ char smh[];
    const uint32_t base = smem_u32(smh);
    const int m0 = blockIdx.y << 7, n0 = blockIdx.x << 7;
    GemmAcc acc;
    gemm_core(A, Bw, smh, H_, m0, n0, base, acc);

    const int lane = threadIdx.x & 31, wid = threadIdx.x >> 5;
    const int wr = (wid >> 1) << 5, wc = (wid & 1) << 6;
    const int lr = lane >> 2, lc = lane & 3;

    float* Cf = 0; __half* Ch = 0; int Nout, coff;
    if (n0 < 2048)      { Cf = Q;  Nout = 2048; coff = n0; }
    else if (n0 < 2560) { Cf = Kp; Nout = 512;  coff = n0 - 2048; }
    else                { Ch = Vh; Nout = 512;  coff = n0 - 2560; }

#pragma unroll
    for (int mi = 0; mi < 2; mi++) {
        const int row = m0 + wr + (mi << 4) + lr;
#pragma unroll
        for (int ni = 0; ni < 8; ni++) {
            const int col = coff + wc + (ni << 3) + (lc << 1);
            if (Cf) {
                float2 v0 = { acc.a[mi][ni][0], acc.a[mi][ni][1] };
                float2 v1 = { acc.a[mi][ni][2], acc.a[mi][ni][3] };
                *(float2*)(Cf + (size_t)row * Nout + col) = v0;
                *(float2*)(Cf + (size_t)(row + 8) * Nout + col) = v1;
            } else {
                __half2 h0 = __floats2half2_rn(acc.a[mi][ni][0], acc.a[mi][ni][1]);
                __half2 h1 = __floats2half2_rn(acc.a[mi][ni][2], acc.a[mi][ni][3]);
                *(__half2*)(Ch + (size_t)row * Nout + col) = h0;
                *(__half2*)(Ch + (size_t)(row + 8) * Nout + col) = h1;
            }
        }
    }
}

// ---------------------------------------------------------------------------
// Fused fp32->fp16 conversion (R8-validated).
// ---------------------------------------------------------------------------
#define CV_HS   1048576
#define CV_WQ   (CV_HS + 524288)
#define CV_WK   (CV_WQ + 131072)
#define CV_WV   (CV_WK + 131072)
#define CV_TOT  (CV_WV + 524288)

__global__ void __launch_bounds__(256) convert_fused(
    const float* __restrict__ hs, const float* __restrict__ Wq,
    const float* __restrict__ Wk, const float* __restrict__ Wv,
    const float* __restrict__ Wo,
    __half* __restrict__ hs_h, __half* __restrict__ wqkv,
    __half* __restrict__ wo_h)
{
    int i = blockIdx.x * blockDim.x + threadIdx.x;
    const float* src; __half* dst; int off;
    if (i < CV_HS)      { src = hs; dst = hs_h;                 off = i; }
    else if (i < CV_WQ) { src = Wq; dst = wqkv;                 off = i - CV_HS; }
    else if (i < CV_WK) { src = Wk; dst = wqkv + 2048u*2048u;   off = i - CV_WQ; }
    else if (i < CV_WV) { src = Wv; dst = wqkv + 2560u*2048u;   off = i - CV_WK; }
    else                { src = Wo; dst = wo_h;                 off = i - CV_WV; }
    float4 a = ((const float4*)src)[2 * off];
    float4 b = ((const float4*)src)[2 * off + 1];
    __half2 h0 = __floats2half2_rn(a.x, a.y);
    __half2 h1 = __floats2half2_rn(a.z, a.w);
    __half2 h2 = __floats2half2_rn(b.x, b.y);
    __half2 h3 = __floats2half2_rn(b.z, b.w);
    uint4 o = { *(uint32_t*)&h0, *(uint32_t*)&h1, *(uint32_t*)&h2, *(uint32_t*)&h3 };
    ((uint4*)dst)[off] = o;
}

// ---------------------------------------------------------------------------
// Fused per-head RMSNorm + RoPE: fp32 in, fp16 out (R7-validated).
// ---------------------------------------------------------------------------
__global__ void norm_rope_h(const float* __restrict__ X, __half* __restrict__ Y,
                            const float* __restrict__ W, int nheads)
{
    const int gw = (blockIdx.x * blockDim.x + threadIdx.x) >> 5;
    const int lane = threadIdx.x & 31;
    const int s = (gw / nheads) % S_;
    const float* xp = X + (size_t)gw * HD_ + lane * 4;
    float4 v = *(const float4*)xp;
    float ss = v.x * v.x + v.y * v.y + v.z * v.z + v.w * v.w;
#pragma unroll
    for (int o = 16; o; o >>= 1) ss += __shfl_xor_sync(0xffffffffu, ss, o);
    const float rms = rsqrtf(ss * (1.0f / HD_) + 1e-6f);
    const float4 w4 = *(const float4*)(W + lane * 4);
    float n[4] = {v.x * rms * w4.x, v.y * rms * w4.y,
                  v.z * rms * w4.z, v.w * rms * w4.w};
    float outv[4];
    const float fp = (float)s;
#pragma unroll
    for (int j = 0; j < 4; j++) {
        float other = __shfl_xor_sync(0xffffffffu, n[j], 16);
        int d = lane * 4 + j;
        int i = d & 63;
        float ang = fp * expf((float)i * -0.14391156831212787f);
        float c, sn;
        sincosf(ang, &sn, &c);
        outv[j] = n[j] * c + ((d < 64) ? -other : other) * sn;
    }
    __half2 h0 = __floats2half2_rn(outv[0], outv[1]);
    __half2 h1 = __floats2half2_rn(outv[2], outv[3]);
    uint2 o2 = { *(uint32_t*)&h0, *(uint32_t*)&h1 };
    *(uint2*)(Y + (size_t)gw * HD_ + lane * 4) = o2;
}

// ---------------------------------------------------------------------------
// fp16 tensor flash attention (R7-validated, unchanged).
// ---------------------------------------------------------------------------
#define F3_Q  0u
#define F3_K  32768u
#define F3_V  49152u
#define F3_P  65536u
#define F3_ST 81920u
#define F3_SMEM (F3_ST + 3072u)

__global__ void __launch_bounds__(256, 1) flash3(const __half* __restrict__ Q,
                                                 const __half* __restrict__ Kv,
                                                 const __half* __restrict__ Vv,
                                                 __half* __restrict__ O)
{
    extern __shared__ char sm3[];
    const uint32_t base = smem_u32(sm3);
    float* sM  = (float*)(sm3 + F3_ST);
    float* sL  = sM + 128;
    float* sRm = sL + 128;
    float* sRs = sRm + 256;

    const int tid = threadIdx.x;
    const int lane = tid & 31, wid = tid >> 5;
    const int lr = lane >> 2, lc = lane & 3;
    const int ql = lane >> 3, rowin = lane & 7;
    const int wr = (wid >> 1) << 5;
    const int wcs = (wid & 1) << 5;
    const int wco = (wid & 1) << 6;
    const int qb = 15 - blockIdx.x;
    const int h = blockIdx.y, b = blockIdx.z;
    const int hkv = h >> 2;
    const float scale = 0.08838834764831845f;

#pragma unroll
    for (int j = 0; j < 8; j++) {
        int idx = (j << 8) + tid;
        int row = idx >> 4, c16 = idx & 15;
        uint4 d4 = *(const uint4*)(Q +
            ((size_t)((b * S_ + (qb << 7) + row) * NH_ + h) << 7) + (c16 << 3));
        uint32_t so = (uint32_t)(row << 8) + (((uint32_t)c16 << 4) ^ ((uint32_t)(row & 7) << 4));
        *(uint4*)(sm3 + F3_Q + so) = d4;
    }
    if (tid < 128) { sM[tid] = -1e30f; sL[tid] = 0.f; }

    float acc_o[2][8][4];
#pragma unroll
    for (int mi = 0; mi < 2; mi++)
#pragma unroll
        for (int ni = 0; ni < 8; ni++)
#pragma unroll
            for (int e = 0; e < 4; e++) acc_o[mi][ni][e] = 0.f;

    const int nkb = (qb << 1) + 2;
    for (int kb = 0; kb < nkb; kb++) {
        __syncthreads();
#pragma unroll
        for (int j = 0; j < 4; j++) {
            int idx = (j << 8) + tid;
            int row = idx >> 4, c16 = idx & 15;
            size_t gb = ((size_t)((b * S_ + (kb << 6) + row) * NKV_ + hkv) << 7) + (c16 << 3);
            uint32_t so = (uint32_t)(row << 8) + (((uint32_t)c16 << 4) ^ ((uint32_t)(row & 7) << 4));
            *(uint4*)(sm3 + F3_K + so) = *(const uint4*)(Kv + gb);
            *(uint4*)(sm3 + F3_V + so) = *(const uint4*)(Vv + gb);
        }
        __syncthreads();

        float acc_s[2][4][4];
#pragma unroll
        for (int mi = 0; mi < 2; mi++)
#pragma unroll
            for (int ni = 0; ni < 4; ni++)
#pragma unroll
                for (int e = 0; e < 4; e++) acc_s[mi][ni][e] = 0.f;
#pragma unroll
        for (int k16 = 0; k16 < 8; k16++) {
            const uint32_t kbb = (uint32_t)(k16 << 5);
            uint32_t af[2][4], bf[4][2];
#pragma unroll
            for (int mi = 0; mi < 2; mi++) {
                int row = wr + (mi << 4) + rowin + ((ql & 1) << 3);
                uint32_t off = (uint32_t)(row << 8) +
                    ((kbb + ((uint32_t)(ql >> 1) << 4)) ^ ((uint32_t)(row & 7) << 4));
                ldmx4(af[mi], base + F3_Q + off);
            }
#pragma unroll
            for (int j = 0; j < 2; j++) {
                int row = wcs + (j << 4) + rowin + ((ql >> 1) << 3);
                uint32_t off = (uint32_t)(row << 8) +
                    ((kbb + ((uint32_t)(ql & 1) << 4)) ^ ((uint32_t)(row & 7) << 4));
                uint32_t r[4];
                ldmx4(r, base + F3_K + off);
                bf[2*j][0] = r[0]; bf[2*j][1] = r[1];
                bf[2*j+1][0] = r[2]; bf[2*j+1][1] = r[3];
            }
#pragma unroll
            for (int mi = 0; mi < 2; mi++)
#pragma unroll
                for (int ni = 0; ni < 4; ni++)
                    mma16816(acc_s[mi][ni], af[mi], bf[ni]);
        }

        float mx[2][2] = { {-1e30f, -1e30f}, {-1e30f, -1e30f} };
#pragma unroll
        for (int mi = 0; mi < 2; mi++) {
            const int r0 = (qb << 7) + wr + (mi << 4) + lr;
#pragma unroll
            for (int ni = 0; ni < 4; ni++) {
                const int c0 = (kb << 6) + wcs + (ni << 3) + (lc << 1);
#pragma unroll
                for (int e = 0; e < 4; e++) {
                    const int rr = r0 + ((e >> 1) << 3);
                    const int cc = c0 + (e & 1);
                    float s = acc_s[mi][ni][e] * scale;
                    if (cc > rr) s = -1e30f;
                    acc_s[mi][ni][e] = s;
                    mx[mi][e >> 1] = fmaxf(mx[mi][e >> 1], s);
                }
            }
        }
#pragma unroll
        for (int mi = 0; mi < 2; mi++)
#pragma unroll
            for (int hh = 0; hh < 2; hh++) {
                mx[mi][hh] = fmaxf(mx[mi][hh], __shfl_xor_sync(0xffffffffu, mx[mi][hh], 1));
                mx[mi][hh] = fmaxf(mx[mi][hh], __shfl_xor_sync(0xffffffffu, mx[mi][hh], 2));
            }
        if (lc == 0) {
#pragma unroll
            for (int mi = 0; mi < 2; mi++) {
                const int rl = wr + (mi << 4) + lr;
                sRm[((wid & 1) << 7) + rl]     = mx[mi][0];
                sRm[((wid & 1) << 7) + rl + 8] = mx[mi][1];
            }
        }
        __syncthreads();

        float mnew[2][2], corr[2][2], sum[2][2] = { {0.f,0.f}, {0.f,0.f} };
#pragma unroll
        for (int mi = 0; mi < 2; mi++)
#pragma unroll
            for (int hh = 0; hh < 2; hh++) {
                const int rl = wr + (mi << 4) + lr + (hh << 3);
                float tmax = fmaxf(sRm[rl], sRm[128 + rl]);
                float mold = sM[rl];
                float mn = fmaxf(mold, tmax);
                mnew[mi][hh] = mn;
                corr[mi][hh] = __expf(mold - mn);
            }
#pragma unroll
        for (int mi = 0; mi < 2; mi++) {
            const int rl0 = wr + (mi << 4) + lr;
#pragma unroll
            for (int ni = 0; ni < 4; ni++) {
                const int col = wcs + (ni << 3) + (lc << 1);
                float p0 = __expf(acc_s[mi][ni][0] - mnew[mi][0]);
                float p1 = __expf(acc_s[mi][ni][1] - mnew[mi][0]);
                float p2 = __expf(acc_s[mi][ni][2] - mnew[mi][1]);
                float p3 = __expf(acc_s[mi][ni][3] - mnew[mi][1]);
                sum[mi][0] += p0 + p1;
                sum[mi][1] += p2 + p3;
                __half2 hp0 = __floats2half2_rn(p0, p1);
                __half2 hp1 = __floats2half2_rn(p2, p3);
                uint32_t so0 = (uint32_t)(rl0 << 7) +
                    (((uint32_t)col << 1) ^ ((uint32_t)(rl0 & 7) << 4));
                uint32_t so1 = (uint32_t)((rl0 + 8) << 7) +
                    (((uint32_t)col << 1) ^ ((uint32_t)((rl0 + 8) & 7) << 4));
                *(__half2*)(sm3 + F3_P + so0) = hp0;
                *(__half2*)(sm3 + F3_P + so1) = hp1;
            }
        }
#pragma unroll
        for (int mi = 0; mi < 2; mi++)
#pragma unroll
            for (int hh = 0; hh < 2; hh++) {
                sum[mi][hh] += __shfl_xor_sync(0xffffffffu, sum[mi][hh], 1);
                sum[mi][hh] += __shfl_xor_sync(0xffffffffu, sum[mi][hh], 2);
            }
        if (lc == 0) {
#pragma unroll
            for (int mi = 0; mi < 2; mi++) {
                const int rl = wr + (mi << 4) + lr;
                sRs[((wid & 1) << 7) + rl]     = sum[mi][0];
                sRs[((wid & 1) << 7) + rl + 8] = sum[mi][1];
            }
        }
#pragma unroll
        for (int mi = 0; mi < 2; mi++)
#pragma unroll
            for (int ni = 0; ni < 8; ni++) {
                acc_o[mi][ni][0] *= corr[mi][0];
                acc_o[mi][ni][1] *= corr[mi][0];
                acc_o[mi][ni][2] *= corr[mi][1];
                acc_o[mi][ni][3] *= corr[mi][1];
            }
        __syncthreads();

        if ((wid & 1) == 0 && lc == 0) {
#pragma unroll
            for (int mi = 0; mi < 2; mi++)
#pragma unroll
                for (int hh = 0; hh < 2; hh++) {
                    const int rl = wr + (mi << 4) + lr + (hh << 3);
                    sL[rl] = sL[rl] * corr[mi][hh] + sRs[rl] + sRs[128 + rl];
                    sM[rl] = mnew[mi][hh];
                }
        }

#pragma unroll
        for (int k16 = 0; k16 < 4; k16++) {
            const uint32_t kbb = (uint32_t)(k16 << 5);
            uint32_t af[2][4], bf[8][2];
#pragma unroll
            for (int mi = 0; mi < 2; mi++) {
                int row = wr + (mi << 4) + rowin + ((ql & 1) << 3);
                uint32_t off = (uint32_t)(row << 7) +
                    ((kbb + ((uint32_t)(ql >> 1) << 4)) ^ ((uint32_t)(row & 7) << 4));
                ldmx4(af[mi], base + F3_P + off);
            }
#pragma unroll
            for (int j = 0; j < 4; j++) {
                int row = (k16 << 4) + rowin + ((ql & 1) << 3);
                uint32_t off = (uint32_t)(row << 8) +
                    ((((uint32_t)(wco + (j << 4)) << 1) + ((uint32_t)(ql >> 1) << 4))
                     ^ ((uint32_t)(row & 7) << 4));
                uint32_t r[4];
                ldmx4t(r, base + F3_V + off);
                bf[2*j][0] = r[0]; bf[2*j][1] = r[1];
                bf[2*j+1][0] = r[2]; bf[2*j+1][1] = r[3];
            }
#pragma unroll
            for (int mi = 0; mi < 2; mi++)
#pragma unroll
                for (int ni = 0; ni < 8; ni++)
                    mma16816(acc_o[mi][ni], af[mi], bf[ni]);
        }
    }

    __syncthreads();
    float invl[2][2];
#pragma unroll
    for (int mi = 0; mi < 2; mi++)
#pragma unroll
        for (int hh = 0; hh < 2; hh++)
            invl[mi][hh] = 1.f / sL[wr + (mi << 4) + lr + (hh << 3)];

#pragma unroll
    for (int mi = 0; mi < 2; mi++) {
        const int rl0 = wr + (mi << 4) + lr;
#pragma unroll
        for (int ni = 0; ni < 8; ni++) {
            const int col = wco + (ni << 3) + (lc << 1);
            size_t b0 = ((size_t)((b * S_ + (qb << 7) + rl0) * NH_ + h) << 7) + col;
            size_t b1 = ((size_t)((b * S_ + (qb << 7) + rl0 + 8) * NH_ + h) << 7) + col;
            __half2 o0 = __floats2half2_rn(acc_o[mi][ni][0] * invl[mi][0],
                                           acc_o[mi][ni][1] * invl[mi][0]);
            __half2 o1 = __floats2half2_rn(acc_o[mi][ni][2] * invl[mi][1],
                                           acc_o[mi][ni][3] * invl[mi][1]);
            *(__half2*)(O + b0) = o0;
            *(__half2*)(O + b1) = o1;
        }
    }
}

// ---------------------------------------------------------------------------

extern "C" void kernel_launch(void* const* d_in, const int* in_sizes, int n_in,
                              void* d_out, int out_size)
{
    const float* hs = (const float*)d_in[0];
    // d_in[1] = attention_mask: exact causal -1e9 mask, applied analytically.
    const float* Wq = (const float*)d_in[2];
    const float* Wk = (const float*)d_in[3];
    const float* Wv = (const float*)d_in[4];
    const float* Wo = (const float*)d_in[5];
    const float* qw = (const float*)d_in[6];
    const float* kw = (const float*)d_in[7];
    float* out = (float*)d_out;

    float *q, *k;
    __half *qh, *kh, *vh, *attn_h, *hs_h, *wqkv_h, *wo_h;
    cudaGetSymbolAddress((void**)&q, g_q);
    cudaGetSymbolAddress((void**)&k, g_k);
    cudaGetSymbolAddress((void**)&qh, g_qh);
    cudaGetSymbolAddress((void**)&kh, g_kh);
    cudaGetSymbolAddress((void**)&vh, g_vh);
    cudaGetSymbolAddress((void**)&attn_h, g_attn_h);
    cudaGetSymbolAddress((void**)&hs_h, g_hs_h);
    cudaGetSymbolAddress((void**)&wqkv_h, g_wqkv_h);
    cudaGetSymbolAddress((void**)&wo_h, g_wo_h);

    cudaFuncSetAttribute(gemm_h,
                         cudaFuncAttributeMaxDynamicSharedMemorySize, GEMMH_SMEM);
    cudaFuncSetAttribute(gemm_qkv,
                         cudaFuncAttributeMaxDynamicSharedMemorySize, GEMMH_SMEM);
    cudaFuncSetAttribute(flash3,
                         cudaFuncAttributeMaxDynamicSharedMemorySize, (int)F3_SMEM);

    // 1) all fp32->fp16 conversions in one launch
    convert_fused<<<CV_TOT / 256, 256>>>(hs, Wq, Wk, Wv, Wo,
                                         hs_h, wqkv_h, wo_h);

    // 2) fused QKV projection (fp16 tensor, fp32 acc; V emitted fp16)
    gemm_qkv<<<dim3(3072/128, M_/128), 256, GEMMH_SMEM>>>(hs_h, wqkv_h, q, k, vh);

    // 3) RMSNorm + RoPE (fp32 in, fp16 out)
    norm_rope_h<<<(M_ * NH_) / 8, 256>>>(q, qh, qw, NH_);
    norm_rope_h<<<(M_ * NKV_) / 8, 256>>>(k, kh, kw, NKV_);

    // 4) fp16 tensor flash attention
    flash3<<<dim3(16, NH_, B_), 256, F3_SMEM>>>(qh, kh, vh, attn_h);

    // 5) out projection (fp16 tensor)
    gemm_h<<<dim3(2048/128, M_/128), 256, GEMMH_SMEM>>>(attn_h, wo_h, out, 2048, H_);
}

// round 11
// speedup vs baseline: 1.2453x; 1.2453x over previous
#include <cuda_runtime.h>
#include <cuda_fp16.h>
#include <math.h>
#include <stdint.h>

#define B_   2
#define S_   2048
#define H_   2048
#define NH_  16
#define NKV_ 4
#define HD_  128
#define M_   (B_*S_)   // 4096

// ---------------------------------------------------------------------------
// Scratch (no allocations allowed) — device globals.
// ---------------------------------------------------------------------------
__device__ float  g_q[(size_t)M_ * NH_ * HD_];      // fp32 Q proj
__device__ float  g_k[(size_t)M_ * NKV_ * HD_];     // fp32 K proj
__device__ __half g_qh[(size_t)M_ * NH_ * HD_];     // fp16 post-norm/rope
__device__ __half g_kh[(size_t)M_ * NKV_ * HD_];
__device__ __half g_vh[(size_t)M_ * NKV_ * HD_];    // fp16 V proj (direct)
__device__ __half g_attn_h[(size_t)M_ * NH_ * HD_];
__device__ __half g_hs_h[(size_t)M_ * H_];
__device__ __half g_wqkv_h[(size_t)3072 * H_];      // [Wq;Wk;Wv] concat rows
__device__ __half g_wo_h[(size_t)H_ * (NH_*HD_)];

// ---------------------------------------------------------------------------
// PTX helpers
// ---------------------------------------------------------------------------
__device__ __forceinline__ uint32_t smem_u32(const void* p) {
    uint32_t a;
    asm("{ .reg .u64 t; cvta.to.shared.u64 t, %1; cvt.u32.u64 %0, t; }"
        : "=r"(a) : "l"(p));
    return a;
}
__device__ __forceinline__ uint32_t swz(uint32_t off) {   // 128B-row swizzle
    return off ^ ((off >> 3) & 0x70);
}
__device__ __forceinline__ void mma16816(float* d, const uint32_t* a,
                                         const uint32_t* b)
{
    asm volatile(
        "mma.sync.aligned.m16n8k16.row.col.f32.f16.f16.f32 "
        "{%0,%1,%2,%3}, {%4,%5,%6,%7}, {%8,%9}, {%0,%1,%2,%3};"
        : "+f"(d[0]), "+f"(d[1]), "+f"(d[2]), "+f"(d[3])
        : "r"(a[0]), "r"(a[1]), "r"(a[2]), "r"(a[3]), "r"(b[0]), "r"(b[1]));
}
__device__ __forceinline__ void ldmx4(uint32_t* r, uint32_t addr) {
    asm volatile("ldmatrix.sync.aligned.m8n8.x4.shared.b16 {%0,%1,%2,%3}, [%4];"
                 : "=r"(r[0]), "=r"(r[1]), "=r"(r[2]), "=r"(r[3]) : "r"(addr));
}
__device__ __forceinline__ void ldmx4t(uint32_t* r, uint32_t addr) {
    asm volatile("ldmatrix.sync.aligned.m8n8.x4.trans.shared.b16 {%0,%1,%2,%3}, [%4];"
                 : "=r"(r[0]), "=r"(r[1]), "=r"(r[2]), "=r"(r[3]) : "r"(addr));
}

// ---------------------------------------------------------------------------
// GEMM core: CTA tile 128(M) x 256(N), BK=64, 8 warps as 2x4 grid of 64x64
// warp tiles. cp.async double buffer (copy path reverted to R8-validated —
// R9 falsified the LDG+STS theory). smem/stage: A 16KB + B 32KB; 2 stages
// = 96KB, 1 CTA/SM. LDSM/HMMA ratio 0.25 (was 0.375).
// K multiple of 64, >= 128. N multiple of 256.
// ---------------------------------------------------------------------------
#define GEMMH_SMEM 98304

struct GemmAcc { float a[4][8][4]; };

__device__ __forceinline__ void gemm_core(const __half* __restrict__ A,
                                          const __half* __restrict__ Bw,
                                          int K, int m0, int n0,
                                          uint32_t base, GemmAcc& acc)
{
    const int tid = threadIdx.x;
    const int lane = tid & 31, wid = tid >> 5;
    const int wr = (wid >> 2) << 6;          // warp rows: 0, 64
    const int wc = (wid & 3) << 6;           // warp cols: 0, 64, 128, 192
    const int KST = K >> 6;

    auto load_stage = [&](int s) {
        const int buf = s & 1;
        const uint32_t ab = base + buf * 49152u;
        const uint32_t bb = ab + 16384u;
        const __half* Ap = A  + (size_t)m0 * K + (s << 6);
        const __half* Bp = Bw + (size_t)n0 * K + (s << 6);
#pragma unroll
        for (int j = 0; j < 4; j++) {        // A: 1024 16B chunks (128 x 64)
            int idx = (j << 8) + tid;
            int row = idx >> 3, c = idx & 7;
            uint32_t so = swz((uint32_t)(row << 7) + (c << 4));
            asm volatile("cp.async.cg.shared.global [%0], [%1], 16;"
                         :: "r"(ab + so), "l"(Ap + (size_t)row * K + (c << 3)));
        }
#pragma unroll
        for (int j = 0; j < 8; j++) {        // B: 2048 16B chunks (256 x 64)
            int idx = (j << 8) + tid;
            int row = idx >> 3, c = idx & 7;
            uint32_t so = swz((uint32_t)(row << 7) + (c << 4));
            asm volatile("cp.async.cg.shared.global [%0], [%1], 16;"
                         :: "r"(bb + so), "l"(Bp + (size_t)row * K + (c << 3)));
        }
        asm volatile("cp.async.commit_group;" ::: "memory");
    };

#pragma unroll
    for (int mi = 0; mi < 4; mi++)
#pragma unroll
        for (int ni = 0; ni < 8; ni++)
#pragma unroll
            for (int e = 0; e < 4; e++) acc.a[mi][ni][e] = 0.f;

    load_stage(0);
    load_stage(1);

    const int ql = lane >> 3, rowin = lane & 7;

    for (int s = 0; s < KST; s++) {
        asm volatile("cp.async.wait_group 1;" ::: "memory");
        __syncthreads();
        const int buf = s & 1;
        const uint32_t ab = base + buf * 49152u;
        const uint32_t bb = ab + 16384u;
#pragma unroll
        for (int k16 = 0; k16 < 4; k16++) {
            const uint32_t kb = (uint32_t)(k16 << 5);
            uint32_t af[4][4], bf[8][2];
#pragma unroll
            for (int mi = 0; mi < 4; mi++) {
                int row = wr + (mi << 4) + rowin + ((ql & 1) << 3);
                uint32_t off = (uint32_t)(row << 7) + kb + ((uint32_t)(ql >> 1) << 4);
                ldmx4(af[mi], ab + swz(off));
            }
#pragma unroll
            for (int j = 0; j < 4; j++) {
                int row = wc + (j << 4) + rowin + ((ql >> 1) << 3);
                uint32_t off = (uint32_t)(row << 7) + kb + ((uint32_t)(ql & 1) << 4);
                uint32_t r[4];
                ldmx4(r, bb + swz(off));
                bf[2*j][0] = r[0]; bf[2*j][1] = r[1];
                bf[2*j+1][0] = r[2]; bf[2*j+1][1] = r[3];
            }
#pragma unroll
            for (int mi = 0; mi < 4; mi++)
#pragma unroll
                for (int ni = 0; ni < 8; ni++)
                    mma16816(acc.a[mi][ni], af[mi], bf[ni]);
        }
        __syncthreads();
        if (s + 2 < KST) load_stage(s + 2);
        else asm volatile("cp.async.commit_group;" ::: "memory");
    }
}

// Generic fp32-output GEMM: C[M,N] = A @ Bw^T  (N % 256 == 0)
__global__ void __launch_bounds__(256, 1) gemm_h(const __half* __restrict__ A,
                                                 const __half* __restrict__ Bw,
                                                 float* __restrict__ C,
                                                 int N, int K)
{
    extern __shared__ char smh[];
    const uint32_t base = smem_u32(smh);
    const int m0 = blockIdx.y << 7, n0 = blockIdx.x << 8;
    GemmAcc acc;
    gemm_core(A, Bw, K, m0, n0, base, acc);

    const int lane = threadIdx.x & 31, wid = threadIdx.x >> 5;
    const int wr = (wid >> 2) << 6, wc = (wid & 3) << 6;
    const int lr = lane >> 2, lc = lane & 3;
#pragma unroll
    for (int mi = 0; mi < 4; mi++) {
        const int row = m0 + wr + (mi << 4) + lr;
#pragma unroll
        for (int ni = 0; ni < 8; ni++) {
            const int col = n0 + wc + (ni << 3) + (lc << 1);
            float2 v0 = { acc.a[mi][ni][0], acc.a[mi][ni][1] };
            float2 v1 = { acc.a[mi][ni][2], acc.a[mi][ni][3] };
            *(float2*)(C + (size_t)row * N + col) = v0;
            *(float2*)(C + (size_t)(row + 8) * N + col) = v1;
        }
    }
}

// Fused QKV projection: Bw = [Wq;Wk;Wv] (3072 rows; regions 2048/512/512 are
// all multiples of 256, so no 256-wide tile straddles regions).
__global__ void __launch_bounds__(256, 1) gemm_qkv(const __half* __restrict__ A,
                                                   const __half* __restrict__ Bw,
                                                   float* __restrict__ Q,
                                                   float* __restrict__ Kp,
                                                   __half* __restrict__ Vh)
{
    extern __shared__ char smh[];
    const uint32_t base = smem_u32(smh);
    const int m0 = blockIdx.y << 7, n0 = blockIdx.x << 8;
    GemmAcc acc;
    gemm_core(A, Bw, H_, m0, n0, base, acc);

    const int lane = threadIdx.x & 31, wid = threadIdx.x >> 5;
    const int wr = (wid >> 2) << 6, wc = (wid & 3) << 6;
    const int lr = lane >> 2, lc = lane & 3;

    float* Cf = 0; __half* Ch = 0; int Nout, coff;
    if (n0 < 2048)      { Cf = Q;  Nout = 2048; coff = n0; }
    else if (n0 < 2560) { Cf = Kp; Nout = 512;  coff = n0 - 2048; }
    else                { Ch = Vh; Nout = 512;  coff = n0 - 2560; }

#pragma unroll
    for (int mi = 0; mi < 4; mi++) {
        const int row = m0 + wr + (mi << 4) + lr;
#pragma unroll
        for (int ni = 0; ni < 8; ni++) {
            const int col = coff + wc + (ni << 3) + (lc << 1);
            if (Cf) {
                float2 v0 = { acc.a[mi][ni][0], acc.a[mi][ni][1] };
                float2 v1 = { acc.a[mi][ni][2], acc.a[mi][ni][3] };
                *(float2*)(Cf + (size_t)row * Nout + col) = v0;
                *(float2*)(Cf + (size_t)(row + 8) * Nout + col) = v1;
            } else {
                __half2 h0 = __floats2half2_rn(acc.a[mi][ni][0], acc.a[mi][ni][1]);
                __half2 h1 = __floats2half2_rn(acc.a[mi][ni][2], acc.a[mi][ni][3]);
                *(__half2*)(Ch + (size_t)row * Nout + col) = h0;
                *(__half2*)(Ch + (size_t)(row + 8) * Nout + col) = h1;
            }
        }
    }
}

// ---------------------------------------------------------------------------
// Fused fp32->fp16 conversion (R8-validated).
// ---------------------------------------------------------------------------
#define CV_HS   1048576
#define CV_WQ   (CV_HS + 524288)
#define CV_WK   (CV_WQ + 131072)
#define CV_WV   (CV_WK + 131072)
#define CV_TOT  (CV_WV + 524288)

__global__ void __launch_bounds__(256) convert_fused(
    const float* __restrict__ hs, const float* __restrict__ Wq,
    const float* __restrict__ Wk, const float* __restrict__ Wv,
    const float* __restrict__ Wo,
    __half* __restrict__ hs_h, __half* __restrict__ wqkv,
    __half* __restrict__ wo_h)
{
    int i = blockIdx.x * blockDim.x + threadIdx.x;
    const float* src; __half* dst; int off;
    if (i < CV_HS)      { src = hs; dst = hs_h;                 off = i; }
    else if (i < CV_WQ) { src = Wq; dst = wqkv;                 off = i - CV_HS; }
    else if (i < CV_WK) { src = Wk; dst = wqkv + 2048u*2048u;   off = i - CV_WQ; }
    else if (i < CV_WV) { src = Wv; dst = wqkv + 2560u*2048u;   off = i - CV_WK; }
    else                { src = Wo; dst = wo_h;                 off = i - CV_WV; }
    float4 a = ((const float4*)src)[2 * off];
    float4 b = ((const float4*)src)[2 * off + 1];
    __half2 h0 = __floats2half2_rn(a.x, a.y);
    __half2 h1 = __floats2half2_rn(a.z, a.w);
    __half2 h2 = __floats2half2_rn(b.x, b.y);
    __half2 h3 = __floats2half2_rn(b.z, b.w);
    uint4 o = { *(uint32_t*)&h0, *(uint32_t*)&h1, *(uint32_t*)&h2, *(uint32_t*)&h3 };
    ((uint4*)dst)[off] = o;
}

// ---------------------------------------------------------------------------
// Fused RMSNorm + RoPE for BOTH Q and K in one launch: fp32 in, fp16 out.
// Warp index < M*NH -> Q row; else K row.
// ---------------------------------------------------------------------------
__global__ void norm_rope_both(const float* __restrict__ Qi,
                               const float* __restrict__ Ki,
                               __half* __restrict__ Qo, __half* __restrict__ Ko,
                               const float* __restrict__ qw,
                               const float* __restrict__ kw)
{
    int gw = (blockIdx.x * blockDim.x + threadIdx.x) >> 5;
    const int lane = threadIdx.x & 31;
    const float* X; __half* Y; const float* W; int nheads, row;
    if (gw < M_ * NH_) { X = Qi; Y = Qo; W = qw; nheads = NH_;  row = gw; }
    else               { X = Ki; Y = Ko; W = kw; nheads = NKV_; row = gw - M_ * NH_; }
    const int s = (row / nheads) % S_;
    const float* xp = X + (size_t)row * HD_ + lane * 4;
    float4 v = *(const float4*)xp;
    float ss = v.x * v.x + v.y * v.y + v.z * v.z + v.w * v.w;
#pragma unroll
    for (int o = 16; o; o >>= 1) ss += __shfl_xor_sync(0xffffffffu, ss, o);
    const float rms = rsqrtf(ss * (1.0f / HD_) + 1e-6f);
    const float4 w4 = *(const float4*)(W + lane * 4);
    float n[4] = {v.x * rms * w4.x, v.y * rms * w4.y,
                  v.z * rms * w4.z, v.w * rms * w4.w};
    float outv[4];
    const float fp = (float)s;
#pragma unroll
    for (int j = 0; j < 4; j++) {
        float other = __shfl_xor_sync(0xffffffffu, n[j], 16);
        int d = lane * 4 + j;
        int i = d & 63;
        float ang = fp * expf((float)i * -0.14391156831212787f);
        float c, sn;
        sincosf(ang, &sn, &c);
        outv[j] = n[j] * c + ((d < 64) ? -other : other) * sn;
    }
    __half2 h0 = __floats2half2_rn(outv[0], outv[1]);
    __half2 h1 = __floats2half2_rn(outv[2], outv[3]);
    uint2 o2 = { *(uint32_t*)&h0, *(uint32_t*)&h1 };
    *(uint2*)(Y + (size_t)row * HD_ + lane * 4) = o2;
}

// ---------------------------------------------------------------------------
// fp16 tensor flash attention (R7-validated, unchanged).
// ---------------------------------------------------------------------------
#define F3_Q  0u
#define F3_K  32768u
#define F3_V  49152u
#define F3_P  65536u
#define F3_ST 81920u
#define F3_SMEM (F3_ST + 3072u)

__global__ void __launch_bounds__(256, 1) flash3(const __half* __restrict__ Q,
                                                 const __half* __restrict__ Kv,
                                                 const __half* __restrict__ Vv,
                                                 __half* __restrict__ O)
{
    extern __shared__ char sm3[];
    const uint32_t base = smem_u32(sm3);
    float* sM  = (float*)(sm3 + F3_ST);
    float* sL  = sM + 128;
    float* sRm = sL + 128;
    float* sRs = sRm + 256;

    const int tid = threadIdx.x;
    const int lane = tid & 31, wid = tid >> 5;
    const int lr = lane >> 2, lc = lane & 3;
    const int ql = lane >> 3, rowin = lane & 7;
    const int wr = (wid >> 1) << 5;
    const int wcs = (wid & 1) << 5;
    const int wco = (wid & 1) << 6;
    const int qb = 15 - blockIdx.x;
    const int h = blockIdx.y, b = blockIdx.z;
    const int hkv = h >> 2;
    const float scale = 0.08838834764831845f;

#pragma unroll
    for (int j = 0; j < 8; j++) {
        int idx = (j << 8) + tid;
        int row = idx >> 4, c16 = idx & 15;
        uint4 d4 = *(const uint4*)(Q +
            ((size_t)((b * S_ + (qb << 7) + row) * NH_ + h) << 7) + (c16 << 3));
        uint32_t so = (uint32_t)(row << 8) + (((uint32_t)c16 << 4) ^ ((uint32_t)(row & 7) << 4));
        *(uint4*)(sm3 + F3_Q + so) = d4;
    }
    if (tid < 128) { sM[tid] = -1e30f; sL[tid] = 0.f; }

    float acc_o[2][8][4];
#pragma unroll
    for (int mi = 0; mi < 2; mi++)
#pragma unroll
        for (int ni = 0; ni < 8; ni++)
#pragma unroll
            for (int e = 0; e < 4; e++) acc_o[mi][ni][e] = 0.f;

    const int nkb = (qb << 1) + 2;
    for (int kb = 0; kb < nkb; kb++) {
        __syncthreads();
#pragma unroll
        for (int j = 0; j < 4; j++) {
            int idx = (j << 8) + tid;
            int row = idx >> 4, c16 = idx & 15;
            size_t gb = ((size_t)((b * S_ + (kb << 6) + row) * NKV_ + hkv) << 7) + (c16 << 3);
            uint32_t so = (uint32_t)(row << 8) + (((uint32_t)c16 << 4) ^ ((uint32_t)(row & 7) << 4));
            *(uint4*)(sm3 + F3_K + so) = *(const uint4*)(Kv + gb);
            *(uint4*)(sm3 + F3_V + so) = *(const uint4*)(Vv + gb);
        }
        __syncthreads();

        float acc_s[2][4][4];
#pragma unroll
        for (int mi = 0; mi < 2; mi++)
#pragma unroll
            for (int ni = 0; ni < 4; ni++)
#pragma unroll
                for (int e = 0; e < 4; e++) acc_s[mi][ni][e] = 0.f;
#pragma unroll
        for (int k16 = 0; k16 < 8; k16++) {
            const uint32_t kbb = (uint32_t)(k16 << 5);
            uint32_t af[2][4], bf[4][2];
#pragma unroll
            for (int mi = 0; mi < 2; mi++) {
                int row = wr + (mi << 4) + rowin + ((ql & 1) << 3);
                uint32_t off = (uint32_t)(row << 8) +
                    ((kbb + ((uint32_t)(ql >> 1) << 4)) ^ ((uint32_t)(row & 7) << 4));
                ldmx4(af[mi], base + F3_Q + off);
            }
#pragma unroll
            for (int j = 0; j < 2; j++) {
                int row = wcs + (j << 4) + rowin + ((ql >> 1) << 3);
                uint32_t off = (uint32_t)(row << 8) +
                    ((kbb + ((uint32_t)(ql & 1) << 4)) ^ ((uint32_t)(row & 7) << 4));
                uint32_t r[4];
                ldmx4(r, base + F3_K + off);
                bf[2*j][0] = r[0]; bf[2*j][1] = r[1];
                bf[2*j+1][0] = r[2]; bf[2*j+1][1] = r[3];
            }
#pragma unroll
            for (int mi = 0; mi < 2; mi++)
#pragma unroll
                for (int ni = 0; ni < 4; ni++)
                    mma16816(acc_s[mi][ni], af[mi], bf[ni]);
        }

        float mx[2][2] = { {-1e30f, -1e30f}, {-1e30f, -1e30f} };
#pragma unroll
        for (int mi = 0; mi < 2; mi++) {
            const int r0 = (qb << 7) + wr + (mi << 4) + lr;
#pragma unroll
            for (int ni = 0; ni < 4; ni++) {
                const int c0 = (kb << 6) + wcs + (ni << 3) + (lc << 1);
#pragma unroll
                for (int e = 0; e < 4; e++) {
                    const int rr = r0 + ((e >> 1) << 3);
                    const int cc = c0 + (e & 1);
                    float s = acc_s[mi][ni][e] * scale;
                    if (cc > rr) s = -1e30f;
                    acc_s[mi][ni][e] = s;
                    mx[mi][e >> 1] = fmaxf(mx[mi][e >> 1], s);
                }
            }
        }
#pragma unroll
        for (int mi = 0; mi < 2; mi++)
#pragma unroll
            for (int hh = 0; hh < 2; hh++) {
                mx[mi][hh] = fmaxf(mx[mi][hh], __shfl_xor_sync(0xffffffffu, mx[mi][hh], 1));
                mx[mi][hh] = fmaxf(mx[mi][hh], __shfl_xor_sync(0xffffffffu, mx[mi][hh], 2));
            }
        if (lc == 0) {
#pragma unroll
            for (int mi = 0; mi < 2; mi++) {
                const int rl = wr + (mi << 4) + lr;
                sRm[((wid & 1) << 7) + rl]     = mx[mi][0];
                sRm[((wid & 1) << 7) + rl + 8] = mx[mi][1];
            }
        }
        __syncthreads();

        float mnew[2][2], corr[2][2], sum[2][2] = { {0.f,0.f}, {0.f,0.f} };
#pragma unroll
        for (int mi = 0; mi < 2; mi++)
#pragma unroll
            for (int hh = 0; hh < 2; hh++) {
                const int rl = wr + (mi << 4) + lr + (hh << 3);
                float tmax = fmaxf(sRm[rl], sRm[128 + rl]);
                float mold = sM[rl];
                float mn = fmaxf(mold, tmax);
                mnew[mi][hh] = mn;
                corr[mi][hh] = __expf(mold - mn);
            }
#pragma unroll
        for (int mi = 0; mi < 2; mi++) {
            const int rl0 = wr + (mi << 4) + lr;
#pragma unroll
            for (int ni = 0; ni < 4; ni++) {
                const int col = wcs + (ni << 3) + (lc << 1);
                float p0 = __expf(acc_s[mi][ni][0] - mnew[mi][0]);
                float p1 = __expf(acc_s[mi][ni][1] - mnew[mi][0]);
                float p2 = __expf(acc_s[mi][ni][2] - mnew[mi][1]);
                float p3 = __expf(acc_s[mi][ni][3] - mnew[mi][1]);
                sum[mi][0] += p0 + p1;
                sum[mi][1] += p2 + p3;
                __half2 hp0 = __floats2half2_rn(p0, p1);
                __half2 hp1 = __floats2half2_rn(p2, p3);
                uint32_t so0 = (uint32_t)(rl0 << 7) +
                    (((uint32_t)col << 1) ^ ((uint32_t)(rl0 & 7) << 4));
                uint32_t so1 = (uint32_t)((rl0 + 8) << 7) +
                    (((uint32_t)col << 1) ^ ((uint32_t)((rl0 + 8) & 7) << 4));
                *(__half2*)(sm3 + F3_P + so0) = hp0;
                *(__half2*)(sm3 + F3_P + so1) = hp1;
            }
        }
#pragma unroll
        for (int mi = 0; mi < 2; mi++)
#pragma unroll
            for (int hh = 0; hh < 2; hh++) {
                sum[mi][hh] += __shfl_xor_sync(0xffffffffu, sum[mi][hh], 1);
                sum[mi][hh] += __shfl_xor_sync(0xffffffffu, sum[mi][hh], 2);
            }
        if (lc == 0) {
#pragma unroll
            for (int mi = 0; mi < 2; mi++) {
                const int rl = wr + (mi << 4) + lr;
                sRs[((wid & 1) << 7) + rl]     = sum[mi][0];
                sRs[((wid & 1) << 7) + rl + 8] = sum[mi][1];
            }
        }
#pragma unroll
        for (int mi = 0; mi < 2; mi++)
#pragma unroll
            for (int ni = 0; ni < 8; ni++) {
                acc_o[mi][ni][0] *= corr[mi][0];
                acc_o[mi][ni][1] *= corr[mi][0];
                acc_o[mi][ni][2] *= corr[mi][1];
                acc_o[mi][ni][3] *= corr[mi][1];
            }
        __syncthreads();

        if ((wid & 1) == 0 && lc == 0) {
#pragma unroll
            for (int mi = 0; mi < 2; mi++)
#pragma unroll
                for (int hh = 0; hh < 2; hh++) {
                    const int rl = wr + (mi << 4) + lr + (hh << 3);
                    sL[rl] = sL[rl] * corr[mi][hh] + sRs[rl] + sRs[128 + rl];
                    sM[rl] = mnew[mi][hh];
                }
        }

#pragma unroll
        for (int k16 = 0; k16 < 4; k16++) {
            const uint32_t kbb = (uint32_t)(k16 << 5);
            uint32_t af[2][4], bf[8][2];
#pragma unroll
            for (int mi = 0; mi < 2; mi++) {
                int row = wr + (mi << 4) + rowin + ((ql & 1) << 3);
                uint32_t off = (uint32_t)(row << 7) +
                    ((kbb + ((uint32_t)(ql >> 1) << 4)) ^ ((uint32_t)(row & 7) << 4));
                ldmx4(af[mi], base + F3_P + off);
            }
#pragma unroll
            for (int j = 0; j < 4; j++) {
                int row = (k16 << 4) + rowin + ((ql & 1) << 3);
                uint32_t off = (uint32_t)(row << 8) +
                    ((((uint32_t)(wco + (j << 4)) << 1) + ((uint32_t)(ql >> 1) << 4))
                     ^ ((uint32_t)(row & 7) << 4));
                uint32_t r[4];
                ldmx4t(r, base + F3_V + off);
                bf[2*j][0] = r[0]; bf[2*j][1] = r[1];
                bf[2*j+1][0] = r[2]; bf[2*j+1][1] = r[3];
            }
#pragma unroll
            for (int mi = 0; mi < 2; mi++)
#pragma unroll
                for (int ni = 0; ni < 8; ni++)
                    mma16816(acc_o[mi][ni], af[mi], bf[ni]);
        }
    }

    __syncthreads();
    float invl[2][2];
#pragma unroll
    for (int mi = 0; mi < 2; mi++)
#pragma unroll
        for (int hh = 0; hh < 2; hh++)
            invl[mi][hh] = 1.f / sL[wr + (mi << 4) + lr + (hh << 3)];

#pragma unroll
    for (int mi = 0; mi < 2; mi++) {
        const int rl0 = wr + (mi << 4) + lr;
#pragma unroll
        for (int ni = 0; ni < 8; ni++) {
            const int col = wco + (ni << 3) + (lc << 1);
            size_t b0 = ((size_t)((b * S_ + (qb << 7) + rl0) * NH_ + h) << 7) + col;
            size_t b1 = ((size_t)((b * S_ + (qb << 7) + rl0 + 8) * NH_ + h) << 7) + col;
            __half2 o0 = __floats2half2_rn(acc_o[mi][ni][0] * invl[mi][0],
                                           acc_o[mi][ni][1] * invl[mi][0]);
            __half2 o1 = __floats2half2_rn(acc_o[mi][ni][2] * invl[mi][1],
                                           acc_o[mi][ni][3] * invl[mi][1]);
            *(__half2*)(O + b0) = o0;
            *(__half2*)(O + b1) = o1;
        }
    }
}

// ---------------------------------------------------------------------------

extern "C" void kernel_launch(void* const* d_in, const int* in_sizes, int n_in,
                              void* d_out, int out_size)
{
    const float* hs = (const float*)d_in[0];
    // d_in[1] = attention_mask: exact causal -1e9 mask, applied analytically.
    const float* Wq = (const float*)d_in[2];
    const float* Wk = (const float*)d_in[3];
    const float* Wv = (const float*)d_in[4];
    const float* Wo = (const float*)d_in[5];
    const float* qw = (const float*)d_in[6];
    const float* kw = (const float*)d_in[7];
    float* out = (float*)d_out;

    float *q, *k;
    __half *qh, *kh, *vh, *attn_h, *hs_h, *wqkv_h, *wo_h;
    cudaGetSymbolAddress((void**)&q, g_q);
    cudaGetSymbolAddress((void**)&k, g_k);
    cudaGetSymbolAddress((void**)&qh, g_qh);
    cudaGetSymbolAddress((void**)&kh, g_kh);
    cudaGetSymbolAddress((void**)&vh, g_vh);
    cudaGetSymbolAddress((void**)&attn_h, g_attn_h);
    cudaGetSymbolAddress((void**)&hs_h, g_hs_h);
    cudaGetSymbolAddress((void**)&wqkv_h, g_wqkv_h);
    cudaGetSymbolAddress((void**)&wo_h, g_wo_h);

    cudaFuncSetAttribute(gemm_h,
                         cudaFuncAttributeMaxDynamicSharedMemorySize, GEMMH_SMEM);
    cudaFuncSetAttribute(gemm_qkv,
                         cudaFuncAttributeMaxDynamicSharedMemorySize, GEMMH_SMEM);
    cudaFuncSetAttribute(flash3,
                         cudaFuncAttributeMaxDynamicSharedMemorySize, (int)F3_SMEM);

    // 1) all fp32->fp16 conversions in one launch
    convert_fused<<<CV_TOT / 256, 256>>>(hs, Wq, Wk, Wv, Wo,
                                         hs_h, wqkv_h, wo_h);

    // 2) fused QKV projection (fp16 tensor, fp32 acc; V emitted fp16)
    gemm_qkv<<<dim3(3072/256, M_/128), 256, GEMMH_SMEM>>>(hs_h, wqkv_h, q, k, vh);

    // 3) RMSNorm + RoPE for Q and K in one launch (fp32 in, fp16 out)
    norm_rope_both<<<(M_ * (NH_ + NKV_)) / 8, 256>>>(q, k, qh, kh, qw, kw);

    // 4) fp16 tensor flash attention
    flash3<<<dim3(16, NH_, B_), 256, F3_SMEM>>>(qh, kh, vh, attn_h);

    // 5) out projection (fp16 tensor)
    gemm_h<<<dim3(2048/256, M_/128), 256, GEMMH_SMEM>>>(attn_h, wo_h, out, 2048, H_);
}

// round 12
// speedup vs baseline: 1.4633x; 1.1751x over previous
#include <cuda_runtime.h>
#include <cuda_fp16.h>
#include <math.h>
#include <stdint.h>

#define B_   2
#define S_   2048
#define H_   2048
#define NH_  16
#define NKV_ 4
#define HD_  128
#define M_   (B_*S_)   // 4096

// ---------------------------------------------------------------------------
// Scratch (no allocations allowed) — device globals.
// ---------------------------------------------------------------------------
__device__ float  g_q[(size_t)M_ * NH_ * HD_];
__device__ float  g_k[(size_t)M_ * NKV_ * HD_];
__device__ __half g_qh[(size_t)M_ * NH_ * HD_];
__device__ __half g_kh[(size_t)M_ * NKV_ * HD_];
__device__ __half g_vh[(size_t)M_ * NKV_ * HD_];
__device__ __half g_attn_h[(size_t)M_ * NH_ * HD_];
__device__ __half g_hs_h[(size_t)M_ * H_];
__device__ __half g_wqkv_h[(size_t)3072 * H_];
__device__ __half g_wo_h[(size_t)H_ * (NH_*HD_)];

// ---------------------------------------------------------------------------
// PTX helpers
// ---------------------------------------------------------------------------
__device__ __forceinline__ uint32_t smem_u32(const void* p) {
    uint32_t a;
    asm("{ .reg .u64 t; cvta.to.shared.u64 t, %1; cvt.u32.u64 %0, t; }"
        : "=r"(a) : "l"(p));
    return a;
}
__device__ __forceinline__ uint32_t swz(uint32_t off) {   // 128B-row swizzle
    return off ^ ((off >> 3) & 0x70);
}
__device__ __forceinline__ void mma16816(float* d, const uint32_t* a,
                                         const uint32_t* b)
{
    asm volatile(
        "mma.sync.aligned.m16n8k16.row.col.f32.f16.f16.f32 "
        "{%0,%1,%2,%3}, {%4,%5,%6,%7}, {%8,%9}, {%0,%1,%2,%3};"
        : "+f"(d[0]), "+f"(d[1]), "+f"(d[2]), "+f"(d[3])
        : "r"(a[0]), "r"(a[1]), "r"(a[2]), "r"(a[3]), "r"(b[0]), "r"(b[1]));
}
__device__ __forceinline__ void ldmx4(uint32_t* r, uint32_t addr) {
    asm volatile("ldmatrix.sync.aligned.m8n8.x4.shared.b16 {%0,%1,%2,%3}, [%4];"
                 : "=r"(r[0]), "=r"(r[1]), "=r"(r[2]), "=r"(r[3]) : "r"(addr));
}
__device__ __forceinline__ void ldmx4t(uint32_t* r, uint32_t addr) {
    asm volatile("ldmatrix.sync.aligned.m8n8.x4.trans.shared.b16 {%0,%1,%2,%3}, [%4];"
                 : "=r"(r[0]), "=r"(r[1]), "=r"(r[2]), "=r"(r[3]) : "r"(addr));
}
__device__ __forceinline__ uint32_t h2u(float a, float b) {
    __half2 h = __floats2half2_rn(a, b);
    return *(uint32_t*)&h;
}

// ---------------------------------------------------------------------------
// GEMM core (R11-validated): CTA 128x256, BK=64, 8 warps 2x4 (64x64 warp
// tiles), cp.async double buffer.
// ---------------------------------------------------------------------------
#define GEMMH_SMEM 98304

struct GemmAcc { float a[4][8][4]; };

__device__ __forceinline__ void gemm_core(const __half* __restrict__ A,
                                          const __half* __restrict__ Bw,
                                          int K, int m0, int n0,
                                          uint32_t base, GemmAcc& acc)
{
    const int tid = threadIdx.x;
    const int lane = tid & 31, wid = tid >> 5;
    const int wr = (wid >> 2) << 6;
    const int wc = (wid & 3) << 6;
    const int KST = K >> 6;

    auto load_stage = [&](int s) {
        const int buf = s & 1;
        const uint32_t ab = base + buf * 49152u;
        const uint32_t bb = ab + 16384u;
        const __half* Ap = A  + (size_t)m0 * K + (s << 6);
        const __half* Bp = Bw + (size_t)n0 * K + (s << 6);
#pragma unroll
        for (int j = 0; j < 4; j++) {
            int idx = (j << 8) + tid;
            int row = idx >> 3, c = idx & 7;
            uint32_t so = swz((uint32_t)(row << 7) + (c << 4));
            asm volatile("cp.async.cg.shared.global [%0], [%1], 16;"
                         :: "r"(ab + so), "l"(Ap + (size_t)row * K + (c << 3)));
        }
#pragma unroll
        for (int j = 0; j < 8; j++) {
            int idx = (j << 8) + tid;
            int row = idx >> 3, c = idx & 7;
            uint32_t so = swz((uint32_t)(row << 7) + (c << 4));
            asm volatile("cp.async.cg.shared.global [%0], [%1], 16;"
                         :: "r"(bb + so), "l"(Bp + (size_t)row * K + (c << 3)));
        }
        asm volatile("cp.async.commit_group;" ::: "memory");
    };

#pragma unroll
    for (int mi = 0; mi < 4; mi++)
#pragma unroll
        for (int ni = 0; ni < 8; ni++)
#pragma unroll
            for (int e = 0; e < 4; e++) acc.a[mi][ni][e] = 0.f;

    load_stage(0);
    load_stage(1);

    const int ql = lane >> 3, rowin = lane & 7;

    for (int s = 0; s < KST; s++) {
        asm volatile("cp.async.wait_group 1;" ::: "memory");
        __syncthreads();
        const int buf = s & 1;
        const uint32_t ab = base + buf * 49152u;
        const uint32_t bb = ab + 16384u;
#pragma unroll
        for (int k16 = 0; k16 < 4; k16++) {
            const uint32_t kb = (uint32_t)(k16 << 5);
            uint32_t af[4][4], bf[8][2];
#pragma unroll
            for (int mi = 0; mi < 4; mi++) {
                int row = wr + (mi << 4) + rowin + ((ql & 1) << 3);
                uint32_t off = (uint32_t)(row << 7) + kb + ((uint32_t)(ql >> 1) << 4);
                ldmx4(af[mi], ab + swz(off));
            }
#pragma unroll
            for (int j = 0; j < 4; j++) {
                int row = wc + (j << 4) + rowin + ((ql >> 1) << 3);
                uint32_t off = (uint32_t)(row << 7) + kb + ((uint32_t)(ql & 1) << 4);
                uint32_t r[4];
                ldmx4(r, bb + swz(off));
                bf[2*j][0] = r[0]; bf[2*j][1] = r[1];
                bf[2*j+1][0] = r[2]; bf[2*j+1][1] = r[3];
            }
#pragma unroll
            for (int mi = 0; mi < 4; mi++)
#pragma unroll
                for (int ni = 0; ni < 8; ni++)
                    mma16816(acc.a[mi][ni], af[mi], bf[ni]);
        }
        __syncthreads();
        if (s + 2 < KST) load_stage(s + 2);
        else asm volatile("cp.async.commit_group;" ::: "memory");
    }
}

__global__ void __launch_bounds__(256, 1) gemm_h(const __half* __restrict__ A,
                                                 const __half* __restrict__ Bw,
                                                 float* __restrict__ C,
                                                 int N, int K)
{
    extern __shared__ char smh[];
    const uint32_t base = smem_u32(smh);
    const int m0 = blockIdx.y << 7, n0 = blockIdx.x << 8;
    GemmAcc acc;
    gemm_core(A, Bw, K, m0, n0, base, acc);

    const int lane = threadIdx.x & 31, wid = threadIdx.x >> 5;
    const int wr = (wid >> 2) << 6, wc = (wid & 3) << 6;
    const int lr = lane >> 2, lc = lane & 3;
#pragma unroll
    for (int mi = 0; mi < 4; mi++) {
        const int row = m0 + wr + (mi << 4) + lr;
#pragma unroll
        for (int ni = 0; ni < 8; ni++) {
            const int col = n0 + wc + (ni << 3) + (lc << 1);
            float2 v0 = { acc.a[mi][ni][0], acc.a[mi][ni][1] };
            float2 v1 = { acc.a[mi][ni][2], acc.a[mi][ni][3] };
            *(float2*)(C + (size_t)row * N + col) = v0;
            *(float2*)(C + (size_t)(row + 8) * N + col) = v1;
        }
    }
}

__global__ void __launch_bounds__(256, 1) gemm_qkv(const __half* __restrict__ A,
                                                   const __half* __restrict__ Bw,
                                                   float* __restrict__ Q,
                                                   float* __restrict__ Kp,
                                                   __half* __restrict__ Vh)
{
    extern __shared__ char smh[];
    const uint32_t base = smem_u32(smh);
    const int m0 = blockIdx.y << 7, n0 = blockIdx.x << 8;
    GemmAcc acc;
    gemm_core(A, Bw, H_, m0, n0, base, acc);

    const int lane = threadIdx.x & 31, wid = threadIdx.x >> 5;
    const int wr = (wid >> 2) << 6, wc = (wid & 3) << 6;
    const int lr = lane >> 2, lc = lane & 3;

    float* Cf = 0; __half* Ch = 0; int Nout, coff;
    if (n0 < 2048)      { Cf = Q;  Nout = 2048; coff = n0; }
    else if (n0 < 2560) { Cf = Kp; Nout = 512;  coff = n0 - 2048; }
    else                { Ch = Vh; Nout = 512;  coff = n0 - 2560; }

#pragma unroll
    for (int mi = 0; mi < 4; mi++) {
        const int row = m0 + wr + (mi << 4) + lr;
#pragma unroll
        for (int ni = 0; ni < 8; ni++) {
            const int col = coff + wc + (ni << 3) + (lc << 1);
            if (Cf) {
                float2 v0 = { acc.a[mi][ni][0], acc.a[mi][ni][1] };
                float2 v1 = { acc.a[mi][ni][2], acc.a[mi][ni][3] };
                *(float2*)(Cf + (size_t)row * Nout + col) = v0;
                *(float2*)(Cf + (size_t)(row + 8) * Nout + col) = v1;
            } else {
                __half2 h0 = __floats2half2_rn(acc.a[mi][ni][0], acc.a[mi][ni][1]);
                __half2 h1 = __floats2half2_rn(acc.a[mi][ni][2], acc.a[mi][ni][3]);
                *(__half2*)(Ch + (size_t)row * Nout + col) = h0;
                *(__half2*)(Ch + (size_t)(row + 8) * Nout + col) = h1;
            }
        }
    }
}

// ---------------------------------------------------------------------------
// Fused fp32->fp16 conversion (R8-validated).
// ---------------------------------------------------------------------------
#define CV_HS   1048576
#define CV_WQ   (CV_HS + 524288)
#define CV_WK   (CV_WQ + 131072)
#define CV_WV   (CV_WK + 131072)
#define CV_TOT  (CV_WV + 524288)

__global__ void __launch_bounds__(256) convert_fused(
    const float* __restrict__ hs, const float* __restrict__ Wq,
    const float* __restrict__ Wk, const float* __restrict__ Wv,
    const float* __restrict__ Wo,
    __half* __restrict__ hs_h, __half* __restrict__ wqkv,
    __half* __restrict__ wo_h)
{
    int i = blockIdx.x * blockDim.x + threadIdx.x;
    const float* src; __half* dst; int off;
    if (i < CV_HS)      { src = hs; dst = hs_h;                 off = i; }
    else if (i < CV_WQ) { src = Wq; dst = wqkv;                 off = i - CV_HS; }
    else if (i < CV_WK) { src = Wk; dst = wqkv + 2048u*2048u;   off = i - CV_WQ; }
    else if (i < CV_WV) { src = Wv; dst = wqkv + 2560u*2048u;   off = i - CV_WK; }
    else                { src = Wo; dst = wo_h;                 off = i - CV_WV; }
    float4 a = ((const float4*)src)[2 * off];
    float4 b = ((const float4*)src)[2 * off + 1];
    __half2 h0 = __floats2half2_rn(a.x, a.y);
    __half2 h1 = __floats2half2_rn(a.z, a.w);
    __half2 h2 = __floats2half2_rn(b.x, b.y);
    __half2 h3 = __floats2half2_rn(b.z, b.w);
    uint4 o = { *(uint32_t*)&h0, *(uint32_t*)&h1, *(uint32_t*)&h2, *(uint32_t*)&h3 };
    ((uint4*)dst)[off] = o;
}

// ---------------------------------------------------------------------------
// Fused RMSNorm + RoPE for Q and K (R11-validated).
// ---------------------------------------------------------------------------
__global__ void norm_rope_both(const float* __restrict__ Qi,
                               const float* __restrict__ Ki,
                               __half* __restrict__ Qo, __half* __restrict__ Ko,
                               const float* __restrict__ qw,
                               const float* __restrict__ kw)
{
    int gw = (blockIdx.x * blockDim.x + threadIdx.x) >> 5;
    const int lane = threadIdx.x & 31;
    const float* X; __half* Y; const float* W; int nheads, row;
    if (gw < M_ * NH_) { X = Qi; Y = Qo; W = qw; nheads = NH_;  row = gw; }
    else               { X = Ki; Y = Ko; W = kw; nheads = NKV_; row = gw - M_ * NH_; }
    const int s = (row / nheads) % S_;
    const float* xp = X + (size_t)row * HD_ + lane * 4;
    float4 v = *(const float4*)xp;
    float ss = v.x * v.x + v.y * v.y + v.z * v.z + v.w * v.w;
#pragma unroll
    for (int o = 16; o; o >>= 1) ss += __shfl_xor_sync(0xffffffffu, ss, o);
    const float rms = rsqrtf(ss * (1.0f / HD_) + 1e-6f);
    const float4 w4 = *(const float4*)(W + lane * 4);
    float n[4] = {v.x * rms * w4.x, v.y * rms * w4.y,
                  v.z * rms * w4.z, v.w * rms * w4.w};
    float outv[4];
    const float fp = (float)s;
#pragma unroll
    for (int j = 0; j < 4; j++) {
        float other = __shfl_xor_sync(0xffffffffu, n[j], 16);
        int d = lane * 4 + j;
        int i = d & 63;
        float ang = fp * expf((float)i * -0.14391156831212787f);
        float c, sn;
        sincosf(ang, &sn, &c);
        outv[j] = n[j] * c + ((d < 64) ? -other : other) * sn;
    }
    __half2 h0 = __floats2half2_rn(outv[0], outv[1]);
    __half2 h1 = __floats2half2_rn(outv[2], outv[3]);
    uint2 o2 = { *(uint32_t*)&h0, *(uint32_t*)&h1 };
    *(uint2*)(Y + (size_t)row * HD_ + lane * 4) = o2;
}

// ---------------------------------------------------------------------------
// flash4 — FA2-style register-resident flash attention.
// CTA: 128 queries x (b,h); 8 warps, each owns 16 query rows x ALL 64 keys.
// Q fragments hoisted to registers; softmax stats in registers (shfl over 4
// lanes); P fed to PV via the C-frag == A-frag layout identity (no smem);
// K/V double-buffered cp.async. Smem: Q stage 32KB + K 2x16KB + V 2x16KB.
// ---------------------------------------------------------------------------
#define F4_Q  0u
#define F4_K  32768u
#define F4_V  (F4_K + 32768u)
#define F4_SMEM (F4_V + 32768u)   // 98304

__global__ void __launch_bounds__(256, 1) flash4(const __half* __restrict__ Q,
                                                 const __half* __restrict__ Kv,
                                                 const __half* __restrict__ Vv,
                                                 __half* __restrict__ O)
{
    extern __shared__ char sm4[];
    const uint32_t base = smem_u32(sm4);

    const int tid = threadIdx.x;
    const int lane = tid & 31, wid = tid >> 5;
    const int lr = lane >> 2, lc = lane & 3;
    const int ql = lane >> 3, rowin = lane & 7;
    const int qb = 15 - blockIdx.x;
    const int h = blockIdx.y, b = blockIdx.z;
    const int hkv = h >> 2;
    const float scale = 0.08838834764831845f;
    const int nkb = (qb << 1) + 2;

    auto load_kv = [&](int kb, int buf) {
#pragma unroll
        for (int j = 0; j < 4; j++) {
            int idx = (j << 8) + tid;          // 1024 chunks per tile
            int row = idx >> 4, c16 = idx & 15;
            size_t gb = ((size_t)((b * S_ + (kb << 6) + row) * NKV_ + hkv) << 7) + (c16 << 3);
            uint32_t so = (uint32_t)(row << 8) +
                (((uint32_t)c16 << 4) ^ ((uint32_t)(row & 7) << 4));
            asm volatile("cp.async.cg.shared.global [%0], [%1], 16;"
                         :: "r"(base + F4_K + buf * 16384u + so), "l"(Kv + gb));
            asm volatile("cp.async.cg.shared.global [%0], [%1], 16;"
                         :: "r"(base + F4_V + buf * 16384u + so), "l"(Vv + gb));
        }
        asm volatile("cp.async.commit_group;" ::: "memory");
    };

    load_kv(0, 0);
    load_kv(1, 1);     // nkb >= 2 always

    // Stage Q tile to smem, then hoist this warp's fragments to registers.
#pragma unroll
    for (int j = 0; j < 8; j++) {
        int idx = (j << 8) + tid;
        int row = idx >> 4, c16 = idx & 15;
        uint4 d4 = *(const uint4*)(Q +
            ((size_t)((b * S_ + (qb << 7) + row) * NH_ + h) << 7) + (c16 << 3));
        uint32_t so = (uint32_t)(row << 8) +
            (((uint32_t)c16 << 4) ^ ((uint32_t)(row & 7) << 4));
        *(uint4*)(sm4 + F4_Q + so) = d4;
    }
    __syncthreads();
    uint32_t qf[8][4];
#pragma unroll
    for (int k16 = 0; k16 < 8; k16++) {
        int row = (wid << 4) + rowin + ((ql & 1) << 3);
        uint32_t off = (uint32_t)(row << 8) +
            ((((uint32_t)k16 << 5) + ((uint32_t)(ql >> 1) << 4)) ^ ((uint32_t)(row & 7) << 4));
        ldmx4(qf[k16], base + F4_Q + off);
    }

    float acc_o[16][4];
#pragma unroll
    for (int ni = 0; ni < 16; ni++)
#pragma unroll
        for (int e = 0; e < 4; e++) acc_o[ni][e] = 0.f;
    float m[2] = { -1e30f, -1e30f }, l[2] = { 0.f, 0.f };

    const int r0g = (qb << 7) + (wid << 4) + lr;   // this lane's row (hh=0)

    for (int s = 0; s < nkb; s++) {
        asm volatile("cp.async.wait_group 1;" ::: "memory");
        __syncthreads();
        const uint32_t kbuf = base + F4_K + (uint32_t)(s & 1) * 16384u;
        const uint32_t vbuf = base + F4_V + (uint32_t)(s & 1) * 16384u;

        // ---- S = Q K^T : warp tile 16 x 64 ----
        float acc_s[8][4];
#pragma unroll
        for (int j8 = 0; j8 < 8; j8++)
#pragma unroll
            for (int e = 0; e < 4; e++) acc_s[j8][e] = 0.f;
#pragma unroll
        for (int k16 = 0; k16 < 8; k16++) {
            const uint32_t kbb = (uint32_t)(k16 << 5);
            uint32_t bf[8][2];
#pragma unroll
            for (int j = 0; j < 4; j++) {
                int row = (j << 4) + rowin + ((ql >> 1) << 3);
                uint32_t off = (uint32_t)(row << 8) +
                    ((kbb + ((uint32_t)(ql & 1) << 4)) ^ ((uint32_t)(row & 7) << 4));
                uint32_t r[4];
                ldmx4(r, kbuf + off);
                bf[2*j][0] = r[0]; bf[2*j][1] = r[1];
                bf[2*j+1][0] = r[2]; bf[2*j+1][1] = r[3];
            }
#pragma unroll
            for (int j8 = 0; j8 < 8; j8++)
                mma16816(acc_s[j8], qf[k16], bf[j8]);
        }

        // ---- scale + causal mask (diagonal blocks only) + row max ----
        float mx[2] = { -1e30f, -1e30f };
        if (s >= nkb - 2) {
#pragma unroll
            for (int j8 = 0; j8 < 8; j8++)
#pragma unroll
                for (int e = 0; e < 4; e++) {
                    int cc = (s << 6) + (j8 << 3) + (lc << 1) + (e & 1);
                    int rr = r0g + ((e >> 1) << 3);
                    float sv = acc_s[j8][e] * scale;
                    if (cc > rr) sv = -1e30f;
                    acc_s[j8][e] = sv;
                    mx[e >> 1] = fmaxf(mx[e >> 1], sv);
                }
        } else {
#pragma unroll
            for (int j8 = 0; j8 < 8; j8++)
#pragma unroll
                for (int e = 0; e < 4; e++) {
                    float sv = acc_s[j8][e] * scale;
                    acc_s[j8][e] = sv;
                    mx[e >> 1] = fmaxf(mx[e >> 1], sv);
                }
        }
#pragma unroll
        for (int hh = 0; hh < 2; hh++) {
            mx[hh] = fmaxf(mx[hh], __shfl_xor_sync(0xffffffffu, mx[hh], 1));
            mx[hh] = fmaxf(mx[hh], __shfl_xor_sync(0xffffffffu, mx[hh], 2));
        }

        // ---- online softmax, all in registers ----
        float corr[2], sum[2] = { 0.f, 0.f };
#pragma unroll
        for (int hh = 0; hh < 2; hh++) {
            float mn = fmaxf(m[hh], mx[hh]);
            corr[hh] = __expf(m[hh] - mn);
            m[hh] = mn;
        }
#pragma unroll
        for (int j8 = 0; j8 < 8; j8++)
#pragma unroll
            for (int e = 0; e < 4; e++) {
                float p = __expf(acc_s[j8][e] - m[e >> 1]);
                sum[e >> 1] += p;
                acc_s[j8][e] = p;
            }
#pragma unroll
        for (int hh = 0; hh < 2; hh++) {
            sum[hh] += __shfl_xor_sync(0xffffffffu, sum[hh], 1);
            sum[hh] += __shfl_xor_sync(0xffffffffu, sum[hh], 2);
            l[hh] = l[hh] * corr[hh] + sum[hh];
        }
#pragma unroll
        for (int ni = 0; ni < 16; ni++) {
            acc_o[ni][0] *= corr[0];
            acc_o[ni][1] *= corr[0];
            acc_o[ni][2] *= corr[1];
            acc_o[ni][3] *= corr[1];
        }

        // ---- P fragments directly from acc_s (C-frag == A-frag identity) ----
        uint32_t pf[4][4];
#pragma unroll
        for (int kv = 0; kv < 4; kv++) {
            pf[kv][0] = h2u(acc_s[2*kv][0],   acc_s[2*kv][1]);
            pf[kv][1] = h2u(acc_s[2*kv][2],   acc_s[2*kv][3]);
            pf[kv][2] = h2u(acc_s[2*kv+1][0], acc_s[2*kv+1][1]);
            pf[kv][3] = h2u(acc_s[2*kv+1][2], acc_s[2*kv+1][3]);
        }

        // ---- O += P V : warp tile 16 x 128, V via trans-ldmatrix ----
#pragma unroll
        for (int kv = 0; kv < 4; kv++) {
            uint32_t bf[16][2];
#pragma unroll
            for (int j = 0; j < 8; j++) {
                int row = (kv << 4) + rowin + ((ql & 1) << 3);
                uint32_t off = (uint32_t)(row << 8) +
                    ((((uint32_t)j << 5) + ((uint32_t)(ql >> 1) << 4))
                     ^ ((uint32_t)(row & 7) << 4));
                uint32_t r[4];
                ldmx4t(r, vbuf + off);
                bf[2*j][0] = r[0]; bf[2*j][1] = r[1];
                bf[2*j+1][0] = r[2]; bf[2*j+1][1] = r[3];
            }
#pragma unroll
            for (int ni = 0; ni < 16; ni++)
                mma16816(acc_o[ni], pf[kv], bf[ni]);
        }

        __syncthreads();
        if (s + 2 < nkb) load_kv(s + 2, s & 1);
        else asm volatile("cp.async.commit_group;" ::: "memory");
    }

    // ---- epilogue: normalize, write fp16 ----
    const float invl0 = 1.f / l[0], invl1 = 1.f / l[1];
    const int rowg = (qb << 7) + (wid << 4) + lr;
#pragma unroll
    for (int ni = 0; ni < 16; ni++) {
        const int col = (ni << 3) + (lc << 1);
        size_t b0 = ((size_t)((b * S_ + rowg) * NH_ + h) << 7) + col;
        size_t b1 = ((size_t)((b * S_ + rowg + 8) * NH_ + h) << 7) + col;
        __half2 o0 = __floats2half2_rn(acc_o[ni][0] * invl0, acc_o[ni][1] * invl0);
        __half2 o1 = __floats2half2_rn(acc_o[ni][2] * invl1, acc_o[ni][3] * invl1);
        *(__half2*)(O + b0) = o0;
        *(__half2*)(O + b1) = o1;
    }
}

// ---------------------------------------------------------------------------

extern "C" void kernel_launch(void* const* d_in, const int* in_sizes, int n_in,
                              void* d_out, int out_size)
{
    const float* hs = (const float*)d_in[0];
    // d_in[1] = attention_mask: exact causal -1e9 mask, applied analytically.
    const float* Wq = (const float*)d_in[2];
    const float* Wk = (const float*)d_in[3];
    const float* Wv = (const float*)d_in[4];
    const float* Wo = (const float*)d_in[5];
    const float* qw = (const float*)d_in[6];
    const float* kw = (const float*)d_in[7];
    float* out = (float*)d_out;

    float *q, *k;
    __half *qh, *kh, *vh, *attn_h, *hs_h, *wqkv_h, *wo_h;
    cudaGetSymbolAddress((void**)&q, g_q);
    cudaGetSymbolAddress((void**)&k, g_k);
    cudaGetSymbolAddress((void**)&qh, g_qh);
    cudaGetSymbolAddress((void**)&kh, g_kh);
    cudaGetSymbolAddress((void**)&vh, g_vh);
    cudaGetSymbolAddress((void**)&attn_h, g_attn_h);
    cudaGetSymbolAddress((void**)&hs_h, g_hs_h);
    cudaGetSymbolAddress((void**)&wqkv_h, g_wqkv_h);
    cudaGetSymbolAddress((void**)&wo_h, g_wo_h);

    cudaFuncSetAttribute(gemm_h,
                         cudaFuncAttributeMaxDynamicSharedMemorySize, GEMMH_SMEM);
    cudaFuncSetAttribute(gemm_qkv,
                         cudaFuncAttributeMaxDynamicSharedMemorySize, GEMMH_SMEM);
    cudaFuncSetAttribute(flash4,
                         cudaFuncAttributeMaxDynamicSharedMemorySize, (int)F4_SMEM);

    // 1) all fp32->fp16 conversions in one launch
    convert_fused<<<CV_TOT / 256, 256>>>(hs, Wq, Wk, Wv, Wo,
                                         hs_h, wqkv_h, wo_h);

    // 2) fused QKV projection
    gemm_qkv<<<dim3(3072/256, M_/128), 256, GEMMH_SMEM>>>(hs_h, wqkv_h, q, k, vh);

    // 3) RMSNorm + RoPE for Q and K
    norm_rope_both<<<(M_ * (NH_ + NKV_)) / 8, 256>>>(q, k, qh, kh, qw, kw);

    // 4) FA2-style flash attention
    flash4<<<dim3(16, NH_, B_), 256, F4_SMEM>>>(qh, kh, vh, attn_h);

    // 5) out projection
    gemm_h<<<dim3(2048/256, M_/128), 256, GEMMH_SMEM>>>(attn_h, wo_h, out, 2048, H_);
}